// round 3
// baseline (speedup 1.0000x reference)
#include <cuda_runtime.h>
#include <cstdint>
#include <cstddef>

// Problem constants (fixed by the dataset):
//   x: [B=64, Cin=64, T=1, K=4096] f32
//   w: [Cin=64, Cout=64, F=4] f32
//   idx: [L=16384] i32,  L = F*K
//   out[b,o,l] = sum_i x[b,i, idx[l]&4095] * w[i,o, idx[l]>>12]
#define B_    64
#define CIN   64
#define K_    4096
#define COUT  64
#define F_    4
#define L_    (F_ * K_)        // 16384

#define LT       256           // l-tile per block
#define THREADS  512
#define WS_FSTRIDE 4100        // floats per f-plane (64*64=4096 + 4 pad -> distinct bank quads per f)
#define XS_STRIDE  65          // 64 + 1 pad -> conflict-lite column reads

// dynamic smem layout (floats):
//   [0, 4*WS_FSTRIDE)                 ws  : w reordered as [f][i][o]
//   [WS_TOT, WS_TOT + LT*XS_STRIDE)   xs  : gathered x columns [l][i]
//   then karr[LT], farr[LT] as ints
#define WS_TOT   (4 * WS_FSTRIDE)
#define XS_TOT   (LT * XS_STRIDE)
#define SMEM_FLOATS (WS_TOT + XS_TOT + 2 * LT)
#define SMEM_BYTES  (SMEM_FLOATS * 4)

// 67 MB transposed x scratch: xt[b][k][i]
__device__ float g_xt[(size_t)B_ * K_ * CIN];

// ---------------------------------------------------------------------------
// Kernel 1: transpose x[b][i][k] -> xt[b][k][i]
// ---------------------------------------------------------------------------
__global__ void transpose_kernel(const float* __restrict__ x) {
    __shared__ float tile[32][33];
    const int b  = blockIdx.z;
    const int i0 = blockIdx.y * 32;
    const int k0 = blockIdx.x * 32;
    const int tx = threadIdx.x;
    const int ty = threadIdx.y;   // block (32, 8)

    const float* xb = x + (size_t)b * CIN * K_;
#pragma unroll
    for (int r = 0; r < 32; r += 8)
        tile[ty + r][tx] = xb[(size_t)(i0 + ty + r) * K_ + (k0 + tx)];
    __syncthreads();

    float* xtb = g_xt + (size_t)b * K_ * CIN;
#pragma unroll
    for (int r = 0; r < 32; r += 8)
        xtb[(size_t)(k0 + ty + r) * CIN + (i0 + tx)] = tile[tx][ty + r];
}

// ---------------------------------------------------------------------------
// f32x2 packed-FMA helpers (Blackwell FFMA2)
// ---------------------------------------------------------------------------
__device__ __forceinline__ void fma2(unsigned long long& acc,
                                     unsigned long long a,
                                     unsigned long long b) {
    asm("fma.rn.f32x2 %0, %1, %2, %0;" : "+l"(acc) : "l"(a), "l"(b));
}
__device__ __forceinline__ unsigned long long pack2(float v) {
    unsigned long long r;
    asm("mov.b64 %0, {%1, %1};" : "=l"(r) : "f"(v));
    return r;
}
__device__ __forceinline__ float2 unpack2(unsigned long long u) {
    float2 r;
    asm("mov.b64 {%0, %1}, %2;" : "=f"(r.x), "=f"(r.y) : "l"(u));
    return r;
}

// ---------------------------------------------------------------------------
// Kernel 2: fused gathered matvec
//   block: (l-tile of 256, batch b). 512 threads = 16 warps.
//   warp w: o_base = (w&3)*16 ; q = lane + 32*(w>>2) ; l0 = 2q, l1 = 2q+1
//   thread computes out[b, o_base..o_base+15, {l0,l1}]  (32 outputs)
// ---------------------------------------------------------------------------
__global__ void __launch_bounds__(THREADS, 1)
fused_kernel(const float* __restrict__ w,
             const int*   __restrict__ idx,
             float*       __restrict__ out) {
    extern __shared__ float sm[];
    float* ws   = sm;                    // [f][i][o], f-stride WS_FSTRIDE
    float* xs   = sm + WS_TOT;           // [l][i], stride XS_STRIDE
    int*   karr = (int*)(xs + XS_TOT);
    int*   farr = karr + LT;

    const int b    = blockIdx.y;
    const int lblk = blockIdx.x * LT;
    const int t    = threadIdx.x;

    // ---- phase A: indices ----
    if (t < LT) {
        int id = idx[lblk + t];
        karr[t] = id & (K_ - 1);
        farr[t] = id >> 12;
    }
    __syncthreads();

    // ---- phase B: stage W and gathered x columns ----
    // w global layout [i][o][f]: float4 over f covers one (i,o) for all 4 f.
    for (int e4 = t; e4 < CIN * COUT; e4 += THREADS) {
        float4 v = ((const float4*)w)[e4];
        int i = e4 >> 6;        // /COUT
        int o = e4 & (COUT - 1);
        int base = i * COUT + o;
        ws[0 * WS_FSTRIDE + base] = v.x;
        ws[1 * WS_FSTRIDE + base] = v.y;
        ws[2 * WS_FSTRIDE + base] = v.z;
        ws[3 * WS_FSTRIDE + base] = v.w;
    }
    {
        // two threads per l; each loads 32 contiguous floats (dense thanks to xt)
        int l    = t >> 1;
        int half = (t & 1) * 32;
        const float4* src = (const float4*)(g_xt + ((size_t)b * K_ + karr[l]) * CIN + half);
        float* dst = xs + l * XS_STRIDE + half;
#pragma unroll
        for (int q = 0; q < 8; q++) {
            float4 v = src[q];
            dst[q * 4 + 0] = v.x;
            dst[q * 4 + 1] = v.y;
            dst[q * 4 + 2] = v.z;
            dst[q * 4 + 3] = v.w;
        }
    }
    __syncthreads();

    // ---- phase C: compute ----
    const int lane   = t & 31;
    const int wrp    = t >> 5;                 // 0..15
    const int o_base = (wrp & 3) << 4;         // 0,16,32,48
    const int q      = ((wrp >> 2) << 5) + lane;  // 0..127
    const int l0     = q << 1;

    const float* xrow0 = xs + l0 * XS_STRIDE;
    const float* xrow1 = xrow0 + XS_STRIDE;
    const float* wp0   = ws + farr[l0]     * WS_FSTRIDE + o_base;
    const float* wp1   = ws + farr[l0 + 1] * WS_FSTRIDE + o_base;

    unsigned long long acc0[8], acc1[8];
#pragma unroll
    for (int p = 0; p < 8; p++) { acc0[p] = 0ULL; acc1[p] = 0ULL; }

#pragma unroll 8
    for (int i = 0; i < CIN; i++) {
        unsigned long long xd0 = pack2(xrow0[i]);
        unsigned long long xd1 = pack2(xrow1[i]);
        const ulonglong2* w0p = (const ulonglong2*)(wp0 + i * COUT);
        const ulonglong2* w1p = (const ulonglong2*)(wp1 + i * COUT);
#pragma unroll
        for (int c = 0; c < 4; c++) {
            ulonglong2 wa = w0p[c];   // (o_base+4c, +4c+1), (+4c+2, +4c+3) for f0
            ulonglong2 wb = w1p[c];   // same columns for f1
            fma2(acc0[2 * c + 0], xd0, wa.x);
            fma2(acc0[2 * c + 1], xd0, wa.y);
            fma2(acc1[2 * c + 0], xd1, wb.x);
            fma2(acc1[2 * c + 1], xd1, wb.y);
        }
    }

    // ---- phase D: epilogue ----
    // acc0[p] = (sum[l0, o_base+2p], sum[l0, o_base+2p+1]); acc1[p] same for l1.
    // Repack to (l0,l1) pairs -> STG.64, lanes stride 8B -> coalesced 256B.
    float* outb = out + (((size_t)b * COUT + o_base) << 14) + (lblk + l0);
#pragma unroll
    for (int p = 0; p < 8; p++) {
        float2 a = unpack2(acc0[p]);
        float2 c = unpack2(acc1[p]);
        float2 s0 = make_float2(a.x, c.x);   // o = o_base + 2p
        float2 s1 = make_float2(a.y, c.y);   // o = o_base + 2p + 1
        *(float2*)(outb + ((size_t)(2 * p)     << 14)) = s0;
        *(float2*)(outb + ((size_t)(2 * p + 1) << 14)) = s1;
    }
}

// ---------------------------------------------------------------------------
extern "C" void kernel_launch(void* const* d_in, const int* in_sizes, int n_in,
                              void* d_out, int out_size) {
    const float* x   = (const float*)d_in[0];
    const float* w   = (const float*)d_in[1];
    const int*   idx = (const int*)d_in[2];
    float*       out = (float*)d_out;
    (void)in_sizes; (void)n_in; (void)out_size;

    cudaFuncSetAttribute(fused_kernel,
                         cudaFuncAttributeMaxDynamicSharedMemorySize, SMEM_BYTES);

    dim3 tgrid(K_ / 32, CIN / 32, B_);
    transpose_kernel<<<tgrid, dim3(32, 8)>>>(x);

    dim3 fgrid(L_ / LT, B_);
    fused_kernel<<<fgrid, THREADS, SMEM_BYTES>>>(w, idx, out);
}

// round 6
// speedup vs baseline: 1.1758x; 1.1758x over previous
#include <cuda_runtime.h>
#include <cstdint>
#include <cstddef>

// Problem constants:
//   x: [B=64, Cin=64, T=1, K=4096] f32
//   w: [Cin=64, Cout=64, F=4] f32
//   idx: [L=16384] i32
//   out[b,o,l] = sum_i x[b,i, idx[l]&4095] * w[i,o, idx[l]>>12]
#define B_    64
#define CIN   64
#define K_    4096
#define COUT  64
#define L_    16384

#define LT       480           // l-tile per block (480/8 + 3 pad-groups <= 63 <= 64 l-threads)
#define THREADS  512
#define WS_FSTRIDE 4104        // 4096 + 8 -> f-planes land 8 banks apart (conflict-free mixed-f loads)
#define NSLOT_ALLOC 512        // >= 480 + 4*6 padding

// smem layout offsets in floats
#define WS_OFF   0
#define XS_OFF   (4 * WS_FSTRIDE)                 // 16416
#define SK_OFF   (XS_OFF + NSLOT_ALLOC * 64)      // + 32768
#define OR_OFF   (SK_OFF + NSLOT_ALLOC)
#define MISC_OFF (OR_OFF + NSLOT_ALLOC)
#define SMEM_FLOATS (MISC_OFF + 32)
#define SMEM_BYTES  (SMEM_FLOATS * 4)             // ~201 KB

#define STAGE_STRIDE 516       // staging rows: 8 x 516 floats (reuses xs region)

// 67 MB transposed x scratch: xt[b][k][i]
__device__ float g_xt[(size_t)B_ * K_ * CIN];

// ---------------------------------------------------------------------------
// Kernel 1: transpose x[b][i][k] -> xt[b][k][i]
// ---------------------------------------------------------------------------
__global__ void transpose_kernel(const float* __restrict__ x) {
    __shared__ float tile[32][33];
    const int b  = blockIdx.z;
    const int i0 = blockIdx.y * 32;
    const int k0 = blockIdx.x * 32;
    const int tx = threadIdx.x;
    const int ty = threadIdx.y;   // block (32, 8)

    const float* xb = x + (size_t)b * CIN * K_;
#pragma unroll
    for (int r = 0; r < 32; r += 8)
        tile[ty + r][tx] = xb[(size_t)(i0 + ty + r) * K_ + (k0 + tx)];
    __syncthreads();

    float* xtb = g_xt + (size_t)b * K_ * CIN;
#pragma unroll
    for (int r = 0; r < 32; r += 8)
        xtb[(size_t)(k0 + ty + r) * CIN + (i0 + tx)] = tile[tx][ty + r];
}

// ---------------------------------------------------------------------------
// f32x2 packed helpers
// ---------------------------------------------------------------------------
__device__ __forceinline__ void fma2(unsigned long long& acc,
                                     unsigned long long a,
                                     unsigned long long b) {
    asm("fma.rn.f32x2 %0, %1, %2, %0;" : "+l"(acc) : "l"(a), "l"(b));
}
__device__ __forceinline__ unsigned long long pack2(float v) {
    unsigned long long r;
    asm("mov.b64 %0, {%1, %1};" : "=l"(r) : "f"(v));
    return r;
}
__device__ __forceinline__ unsigned long long pack_pair(float a, float b) {
    unsigned long long r;
    asm("mov.b64 %0, {%1, %2};" : "=l"(r) : "f"(a), "f"(b));
    return r;
}
__device__ __forceinline__ float2 unpack2(unsigned long long u) {
    float2 r;
    asm("mov.b64 {%0, %1}, %2;" : "=f"(r.x), "=f"(r.y) : "l"(u));
    return r;
}

// ---------------------------------------------------------------------------
// Kernel 2: fused gathered matvec, f-sorted per block.
//   block: (l-tile of 480, batch b), 512 threads.
//   thread t: l-thread sg = t&63 owns 8 sorted slots [8sg, 8sg+8) (uniform f);
//             o-group oc = t>>6 owns o in {oc, oc+8, ..., oc+56}.
//   acc[j][p]: f32x2 over l-pair p (slots 8sg+2p, +2p+1) for o = oc + 8j.
// ---------------------------------------------------------------------------
__global__ void __launch_bounds__(THREADS, 1)
fused_kernel(const float* __restrict__ w,
             const int*   __restrict__ idx,
             float*       __restrict__ out) {
    extern __shared__ float sm[];
    float* ws      = sm + WS_OFF;
    float* xs      = sm + XS_OFF;
    int*   sortedK = (int*)(sm + SK_OFF);
    int*   orig    = (int*)(sm + OR_OFF);
    int*   misc    = (int*)(sm + MISC_OFF);
    int*   cnt     = misc;        // [4]
    int*   cnt2    = misc + 4;    // [4]
    int*   base    = misc + 8;    // [5]

    const int t    = threadIdx.x;
    const int b    = blockIdx.y;
    const int lblk = blockIdx.x * LT;
    const int LTa  = min(LT, L_ - lblk);

    // ---- init ----
    if (t < 8) misc[t] = 0;
    if (t < NSLOT_ALLOC) { orig[t] = -1; sortedK[t] = 0; }
    __syncthreads();

    // ---- histogram ----
    int myk = 0, myf = 0;
    if (t < LTa) {
        int id = idx[lblk + t];
        myk = id & (K_ - 1);
        myf = id >> 12;
        atomicAdd(&cnt[myf], 1);
    }
    __syncthreads();
    if (t == 0) {
        int acc = 0;
        base[0] = 0;
#pragma unroll
        for (int f = 0; f < 4; f++) { acc += (cnt[f] + 7) & ~7; base[f + 1] = acc; }
    }
    __syncthreads();

    // ---- scatter into padded buckets ----
    if (t < LTa) {
        int r = atomicAdd(&cnt2[myf], 1);
        int s = base[myf] + r;
        sortedK[s] = myk;
        orig[s]    = t;
    }

    // ---- stage W as ws[f][i][o], f-stride 4104 ----
    {
        const float4* w4 = (const float4*)w;   // [i][o] over f
        for (int e = t; e < CIN * COUT; e += THREADS) {
            float4 v = w4[e];
            int p = (e >> 6) * 64 + (e & 63);
            ws[0 * WS_FSTRIDE + p] = v.x;
            ws[1 * WS_FSTRIDE + p] = v.y;
            ws[2 * WS_FSTRIDE + p] = v.z;
            ws[3 * WS_FSTRIDE + p] = v.w;
        }
    }
    __syncthreads();

    const int nSlots = base[4];
    const int nG     = nSlots >> 3;

    // ---- gather x columns into xs with per-slot rotation (i + slot>>3)&63 ----
    if (t < nSlots) {
        const float4* src = (const float4*)(g_xt + ((size_t)b * K_ + sortedK[t]) * CIN);
        float* dst = xs + t * 64;
        const int rot = (t >> 3) & 63;
        const int pr  = t & 7;
#pragma unroll
        for (int mp = 0; mp < 8; mp++) {
            int qp = ((mp + pr) & 7) * 2;      // 32B-aligned pair of float4s
#pragma unroll
            for (int e = 0; e < 2; e++) {
                float4 v = src[qp + e];
                int i0 = (qp + e) * 4;
                dst[(i0 + 0 + rot) & 63] = v.x;
                dst[(i0 + 1 + rot) & 63] = v.y;
                dst[(i0 + 2 + rot) & 63] = v.z;
                dst[(i0 + 3 + rot) & 63] = v.w;
            }
        }
    }
    __syncthreads();

    // ---- compute ----
    const int  sg     = t & 63;
    const int  oc     = t >> 6;
    const bool active = (sg < nG);
    const int  s0     = sg << 3;

    unsigned long long acc[8][4];
#pragma unroll
    for (int j = 0; j < 8; j++)
#pragma unroll
        for (int p = 0; p < 4; p++) acc[j][p] = 0ull;

    if (active) {
        const int fg = (s0 >= base[1]) + (s0 >= base[2]) + (s0 >= base[3]);
        const float* xp = xs + s0 * 64;
        const float* wp = ws + fg * WS_FSTRIDE + oc;
#pragma unroll 2
        for (int i = 0; i < CIN; i++) {
            const int off = (i + sg) & 63;
            unsigned long long xd[4];
#pragma unroll
            for (int p = 0; p < 4; p++) {
                float a = xp[(2 * p)     * 64 + off];
                float c = xp[(2 * p + 1) * 64 + off];
                xd[p] = pack_pair(a, c);
            }
            const float* wr = wp + i * 64;
#pragma unroll
            for (int j = 0; j < 8; j++) {
                unsigned long long wd = pack2(wr[8 * j]);
#pragma unroll
                for (int p = 0; p < 4; p++) fma2(acc[j][p], xd[p], wd);
            }
        }
    }

    // ---- staging + coalesced store, 8 o-chunks ----
    float* staged = xs;                         // 8 rows x STAGE_STRIDE, reuses xs
    float* outb = out + ((size_t)b * COUT) * L_ + lblk;
    const int c2   = t & 127;
    const int orow = t >> 7;                    // 0..3

    for (int j = 0; j < 8; j++) {
        __syncthreads();                        // prev chunk reads done / compute done
        if (active) {
#pragma unroll
            for (int g = 0; g < 8; g++) {
                int og = orig[s0 + g];
                if (og >= 0) {
                    float2 u = unpack2(acc[j][g >> 1]);
                    staged[oc * STAGE_STRIDE + og] = (g & 1) ? u.y : u.x;
                }
            }
        }
        __syncthreads();
        if (4 * c2 < LTa) {
#pragma unroll
            for (int h = 0; h < 2; h++) {
                int r = orow + 4 * h;           // row within chunk, o = 8j + r
                float4 v = *(const float4*)(staged + r * STAGE_STRIDE + 4 * c2);
                *(float4*)(outb + (size_t)(8 * j + r) * L_ + 4 * c2) = v;
            }
        }
    }
}

// ---------------------------------------------------------------------------
extern "C" void kernel_launch(void* const* d_in, const int* in_sizes, int n_in,
                              void* d_out, int out_size) {
    const float* x   = (const float*)d_in[0];
    const float* w   = (const float*)d_in[1];
    const int*   idx = (const int*)d_in[2];
    float*       out = (float*)d_out;
    (void)in_sizes; (void)n_in; (void)out_size;

    cudaFuncSetAttribute(fused_kernel,
                         cudaFuncAttributeMaxDynamicSharedMemorySize, SMEM_BYTES);

    dim3 tgrid(K_ / 32, CIN / 32, B_);
    transpose_kernel<<<tgrid, dim3(32, 8)>>>(x);

    const int nblk = (L_ + LT - 1) / LT;        // 35
    dim3 fgrid(nblk, B_);
    fused_kernel<<<fgrid, THREADS, SMEM_BYTES>>>(w, idx, out);
}

// round 7
// speedup vs baseline: 2.1899x; 1.8625x over previous
#include <cuda_runtime.h>
#include <cstdint>
#include <cstddef>

// Problem constants:
//   x: [B=64, Cin=64, T=1, K=4096] f32
//   w: [Cin=64, Cout=64, F=4] f32
//   idx: [L=16384] i32
//   out[b,o,l] = res_flat[b,o,idx[l]],  res[b,o,f,k] = sum_i x[b,i,k]*w[i,o,f]
#define B_    64
#define CIN   64
#define K_    4096
#define COUT  64
#define F_    4
#define L_    16384

// 268 MB scratch: res[b][o][f][k]  (l = f*4096 + k contiguous per (b,o) plane)
__device__ float g_res[(size_t)B_ * COUT * F_ * K_];

// ---------------------------------------------------------------------------
// f32x2 FMA
// ---------------------------------------------------------------------------
__device__ __forceinline__ void fma2(unsigned long long& acc,
                                     unsigned long long a,
                                     unsigned long long b) {
    asm("fma.rn.f32x2 %0, %1, %2, %0;" : "+l"(acc) : "l"(a), "l"(b));
}

// ---------------------------------------------------------------------------
// Kernel 1: dense GEMM  res[b, m=(o*4+f), k] = sum_i w[i,o,f] * x[b,i,k]
//   grid (16 ktiles, 4 mtiles, 64 b), 256 threads, 2 CTAs/SM.
//   Block tile: M=64 rows x N=256 k.
//   Thread (kt = t&31, rt = t>>5): rows rt*8..rt*8+7, k = 4*kt + {0..3} + 128*{0,1}.
//   ws holds w pair-DUPLICATED: ws[i][2m]=ws[i][2m+1]=w[i,m]  ->
//   uniform LDS.128 yields ready-made f32x2 broadcast operands (no MOV packing).
// ---------------------------------------------------------------------------
#define GT 256
#define XS_STRIDE 260                       // 256 + 4 pad: staggers store banks
#define WS_SZ (CIN * 128)                   // 64 * 128 dup floats = 32 KB
#define XS_SZ (CIN * XS_STRIDE)             // ~66.6 KB
#define GSM_BYTES ((WS_SZ + XS_SZ) * 4)     // ~97 KB -> 2 CTAs/SM

__global__ void __launch_bounds__(GT, 2)
gemm_kernel(const float* __restrict__ x, const float* __restrict__ w) {
    extern __shared__ float sm[];
    float* ws = sm;            // [i][128]  duplicated row pairs
    float* xs = sm + WS_SZ;    // [i][260]

    const int t   = threadIdx.x;
    const int kt0 = blockIdx.x * 256;
    const int m0  = blockIdx.y * 64;
    const int b   = blockIdx.z;
    const int o0  = m0 >> 2;

    // ---- stage W (dup pairs): block needs o in [o0, o0+16), all f, all i ----
    {
        const float4* w4 = (const float4*)w;          // [i][o] over f
        for (int e = t; e < CIN * 16; e += GT) {
            int i = e >> 4, ol = e & 15;
            float4 v = w4[i * COUT + o0 + ol];
            float* dst = ws + i * 128 + ol * 8;       // m_local = ol*4+f -> dup idx 2*m
            dst[0] = v.x; dst[1] = v.x;
            dst[2] = v.y; dst[3] = v.y;
            dst[4] = v.z; dst[5] = v.z;
            dst[6] = v.w; dst[7] = v.w;
        }
    }
    // ---- stage x tile [64 i][256 k] ----
    {
        const float4* x4 = (const float4*)x;
        const int kq0 = kt0 >> 2;
#pragma unroll
        for (int r = 0; r < 16; r++) {
            int q  = t + GT * r;                      // 0..4095
            int i  = q >> 6, c4 = q & 63;
            float4 v = x4[((size_t)(b * CIN + i) << 10) + kq0 + c4];
            *(float4*)(xs + i * XS_STRIDE + 4 * c4) = v;
        }
    }
    __syncthreads();

    // ---- compute ----
    const int kt = t & 31;
    const int rt = t >> 5;

    unsigned long long acc[8][4];
#pragma unroll
    for (int j = 0; j < 8; j++)
#pragma unroll
        for (int c = 0; c < 4; c++) acc[j][c] = 0ull;

    const float* wsr = ws + rt * 16;
    const float* xsr = xs + 4 * kt;

#pragma unroll 4
    for (int i = 0; i < CIN; i++) {
        // 4 uniform broadcast LDS.128: w pairs for rows rt*8 .. rt*8+7
        const ulonglong2* wq = (const ulonglong2*)(wsr + i * 128);
        ulonglong2 w01 = wq[0], w23 = wq[1], w45 = wq[2], w67 = wq[3];
        // 2 LDS.128: k quads (pairs (4kt,4kt+1),(4kt+2,4kt+3)) at c=0,1
        ulonglong2 xa = *(const ulonglong2*)(xsr + i * XS_STRIDE);
        ulonglong2 xb = *(const ulonglong2*)(xsr + i * XS_STRIDE + 128);

        unsigned long long wj[8] = { w01.x, w01.y, w23.x, w23.y,
                                     w45.x, w45.y, w67.x, w67.y };
#pragma unroll
        for (int j = 0; j < 8; j++) {
            fma2(acc[j][0], xa.x, wj[j]);
            fma2(acc[j][1], xa.y, wj[j]);
            fma2(acc[j][2], xb.x, wj[j]);
            fma2(acc[j][3], xb.y, wj[j]);
        }
    }

    // ---- store to res (STG.128, coalesced 16B-lane-stride) ----
#pragma unroll
    for (int j = 0; j < 8; j++) {
        int m = m0 + rt * 8 + j;
        int o = m >> 2, f = m & 3;
        float* dst = g_res + ((((size_t)b * COUT + o) * F_ + f) << 12) + kt0 + 4 * kt;
        ulonglong2 v0; v0.x = acc[j][0]; v0.y = acc[j][1];
        ulonglong2 v1; v1.x = acc[j][2]; v1.y = acc[j][3];
        *(ulonglong2*)(dst)       = v0;
        *(ulonglong2*)(dst + 128) = v1;
    }
}

// ---------------------------------------------------------------------------
// Kernel 2: per-plane gather. block = (b,o) plane (64 KB), 256 threads.
// ---------------------------------------------------------------------------
#define HT 256

__global__ void __launch_bounds__(HT, 2)
gather_kernel(const int* __restrict__ idx, float* __restrict__ out) {
    extern __shared__ float plane[];   // 16384 floats = 64 KB
    const int t = threadIdx.x;
    const int p = blockIdx.x;          // b*64 + o

    const float4* src4 = (const float4*)(g_res + (size_t)p * L_);
    float4*       pl4  = (float4*)plane;
#pragma unroll
    for (int r = 0; r < 16; r++)
        pl4[t + HT * r] = __ldcs(src4 + t + HT * r);
    __syncthreads();

    const int4* idx4 = (const int4*)idx;
    float4*     dst4 = (float4*)(out + (size_t)p * L_);
#pragma unroll 4
    for (int r = 0; r < 16; r++) {
        int4 id = idx4[t + HT * r];
        float4 v;
        v.x = plane[id.x];
        v.y = plane[id.y];
        v.z = plane[id.z];
        v.w = plane[id.w];
        __stcs(dst4 + t + HT * r, v);
    }
}

// ---------------------------------------------------------------------------
extern "C" void kernel_launch(void* const* d_in, const int* in_sizes, int n_in,
                              void* d_out, int out_size) {
    const float* x   = (const float*)d_in[0];
    const float* w   = (const float*)d_in[1];
    const int*   idx = (const int*)d_in[2];
    float*       out = (float*)d_out;
    (void)in_sizes; (void)n_in; (void)out_size;

    cudaFuncSetAttribute(gemm_kernel,
                         cudaFuncAttributeMaxDynamicSharedMemorySize, GSM_BYTES);
    cudaFuncSetAttribute(gather_kernel,
                         cudaFuncAttributeMaxDynamicSharedMemorySize, L_ * 4);

    dim3 ggrid(K_ / 256, 4, B_);                 // 16 x 4 x 64 = 4096 blocks
    gemm_kernel<<<ggrid, GT, GSM_BYTES>>>(x, w);

    gather_kernel<<<B_ * COUT, HT, L_ * 4>>>(idx, out);
}